// round 15
// baseline (speedup 1.0000x reference)
#include <cuda_runtime.h>
#include <cuda_fp16.h>
#include <cstdint>

// -------------------------- problem constants ------------------------------
#define NN 32768        // rows (B*H*W)
#define DD 256          // embedding dim
#define KK 8192         // codebook size
#define BM 64           // rows per CTA (pass-1)
#define BN 128          // codes per n-tile
#define NTILES (KK / BN)            // 64
#define BSPT 4                      // B-stages per tile (K-chunks of 64)
#define NBSTG (NTILES * BSPT)       // 256
#define NCTA_MAIN (NN / BM)         // 512
#define NCTA_FIN  256               // vq_fin grid (128 rows each)

#define OUT_OFF  0
#define LOSS_OFF 8388608
#define IDX_OFF  8388609

#define A_BYTES  32768              // 4 h1 chunks x 8 KB, resident
#define B_SLOT   16384              // one B chunk: 128 rows x 128 B
#define B_BASE   A_BYTES
#define SMEM_DYN (A_BYTES + 2 * B_SLOT)   // 65536 -> 3 CTAs/SM

#define ESCALE 65536.0f             // e pre-scale 2^16 (exact)
#define FNEGINF __int_as_float(0xff800000)
#define FINF    __int_as_float(0x7f800000)

__device__ float  g_xs[NN];
__device__ double g_part[NCTA_FIN];
__device__ int    g_cand[NN * 8];
__device__ int    g_fidx[NN];
__device__ __align__(16) float  g_xT[(size_t)NN * DD];      // row-major x copy
// fp16 screening operands, chunk-major [chunk][row][64 halves] (128 B/row)
__device__ __align__(16) __half g_Ah[(size_t)4 * NN * 64];  // h1 = fp16(x)
__device__ __align__(16) __half g_Eh[(size_t)4 * KK * 64];  // c1 = fp16(e*2^16)

// ---------------------------- asm helpers ----------------------------------
__device__ __forceinline__ uint32_t smem_u32(const void* p) {
    uint32_t a;
    asm("{ .reg .u64 t; cvta.to.shared.u64 t, %1; cvt.u32.u64 %0, t; }" : "=r"(a) : "l"(p));
    return a;
}
#define CPA(dst, src) asm volatile("cp.async.cg.shared.global [%0], [%1], 16;" :: "r"(dst), "l"(src))
#define CPC()         asm volatile("cp.async.commit_group;" ::: "memory")
#define CPW(n)        asm volatile("cp.async.wait_group %0;" :: "n"(n) : "memory")

__device__ __forceinline__ void ldsm4(uint32_t* r, uint32_t addr) {
    asm volatile("ldmatrix.sync.aligned.m8n8.x4.shared.b16 {%0,%1,%2,%3}, [%4];"
        : "=r"(r[0]), "=r"(r[1]), "=r"(r[2]), "=r"(r[3]) : "r"(addr));
}
__device__ __forceinline__ void mma_fp16(float* c, const uint32_t* a, const uint32_t* b) {
    asm volatile("mma.sync.aligned.m16n8k16.row.col.f32.f16.f16.f32 "
        "{%0,%1,%2,%3}, {%4,%5,%6,%7}, {%8,%9}, {%0,%1,%2,%3};"
        : "+f"(c[0]), "+f"(c[1]), "+f"(c[2]), "+f"(c[3])
        : "r"(a[0]), "r"(a[1]), "r"(a[2]), "r"(a[3]), "r"(b[0]), "r"(b[1]));
}
// D = A*B + 0 (separate zero C: resets the accumulator without MOVs)
__device__ __forceinline__ void mma_fp16_z(float* c, const uint32_t* a, const uint32_t* b) {
    asm volatile("mma.sync.aligned.m16n8k16.row.col.f32.f16.f16.f32 "
        "{%0,%1,%2,%3}, {%4,%5,%6,%7}, {%8,%9}, {%10,%10,%10,%10};"
        : "=f"(c[0]), "=f"(c[1]), "=f"(c[2]), "=f"(c[3])
        : "r"(a[0]), "r"(a[1]), "r"(a[2]), "r"(a[3]), "r"(b[0]), "r"(b[1]), "f"(0.f));
}

// ---------------------------------------------------------------------------
// prep kernels
// ---------------------------------------------------------------------------
__global__ void vq_xs(const float* __restrict__ x) {
    int n = blockIdx.x * blockDim.x + threadIdx.x;
    if (n >= NN) return;
    int b = n >> 10, c = n & 1023;
    const float* xb = x + (size_t)b * (DD * 1024) + c;
    float s = 0.f;
#pragma unroll 8
    for (int d = 0; d < DD; d++) { float v = xb[(size_t)d * 1024]; s = fmaf(v, v, s); }
    g_xs[n] = s;
}

// x split: grid 1024 = 8 d-slices(32) x 128 row-blocks(256); smem transpose
__global__ void vq_split_x(const float* __restrict__ x) {
    __shared__ float sx[32][257];
    const int t  = threadIdx.x;
    const int dc = blockIdx.x & 7;
    const int nb = blockIdx.x >> 3;
    const int n0 = nb * 256;
    const int b  = n0 >> 10, hw0 = n0 & 1023;
    const float* xb = x + (size_t)b * (DD * 1024) + (size_t)(dc * 32) * 1024 + hw0;
#pragma unroll
    for (int dd = 0; dd < 32; dd++) sx[dd][t] = xb[(size_t)dd * 1024 + t];
    __syncthreads();

    float* xrow = g_xT + (size_t)(n0 + t) * DD + dc * 32;
#pragma unroll
    for (int q = 0; q < 8; q++)
        *(float4*)(xrow + 4 * q) = make_float4(sx[4 * q][t], sx[4 * q + 1][t],
                                               sx[4 * q + 2][t], sx[4 * q + 3][t]);
    uint32_t p1[16];
#pragma unroll
    for (int u = 0; u < 16; u++) {
        uint32_t h0 = (uint32_t)__half_as_ushort(__float2half_rn(sx[2 * u][t]));
        uint32_t h1 = (uint32_t)__half_as_ushort(__float2half_rn(sx[2 * u + 1][t]));
        p1[u] = h0 | (h1 << 16);
    }
    __half* d1 = g_Ah + ((size_t)(dc >> 1) * NN + n0 + t) * 64 + (dc & 1) * 32;
#pragma unroll
    for (int p = 0; p < 4; p++)
        *(uint4*)(d1 + 8 * p) = make_uint4(p1[4 * p], p1[4 * p + 1], p1[4 * p + 2], p1[4 * p + 3]);
}

// emb split: 1 warp per code row; c1 = fp16(e*2^16)
__global__ void vq_split_e(const float* __restrict__ emb) {
    int wid = threadIdx.x >> 5, lane = threadIdx.x & 31;
    int k = blockIdx.x * 8 + wid;
    const float* er = emb + (size_t)k * DD;
#pragma unroll
    for (int dc = 0; dc < 8; dc++) {
        float es = __fmul_rn(er[dc * 32 + lane], ESCALE);
        g_Eh[((size_t)(dc >> 1) * KK + k) * 64 + (dc & 1) * 32 + lane] = __float2half_rn(es);
    }
}

// ---------------------------------------------------------------------------
// issue helpers (XOR-swizzled 16B granules)
// ---------------------------------------------------------------------------
__device__ __forceinline__ void issueA(uint32_t sb, int rt, int tid) {
#pragma unroll
    for (int p = 0; p < 8; p++) {
        int i = tid + p * 256;
        int chunk = i >> 9, gi = i & 511, row = gi >> 3, gg = gi & 7;
        const char* src = (const char*)g_Ah +
            ((size_t)chunk * NN + (size_t)rt * BM + row) * 128 + gg * 16;
        CPA(sb + chunk * 8192 + row * 128 + ((gg ^ (row & 7)) << 4), src);
    }
}
// B-stage g: tile g>>2, K-chunk g&3 (16 KB = 128 rows, 4 granules/thread)
__device__ __forceinline__ void issueB(uint32_t sb, int slot, int g, int tid) {
    const int ti = g >> 2, bc = g & 3;
    const char* bSrc = (const char*)g_Eh + ((size_t)bc * KK + (size_t)ti * BN) * 128;
    const uint32_t bDst = sb + B_BASE + slot * B_SLOT;
#pragma unroll
    for (int p = 0; p < 4; p++) {
        int i = tid + p * 256, row = i >> 3, gg = i & 7;
        CPA(bDst + row * 128 + ((gg ^ (row & 7)) << 4), bSrc + (size_t)i * 16);
    }
}

// consume: one A chunk (64 rows, K=64) vs one B chunk (128 codes), warp n=32
template <bool FIRST>
__device__ __forceinline__ void consume(uint32_t aS, uint32_t bS, int wm, int wn,
                                        int lane, float (&acc)[2][4][4]) {
    const int grp = lane >> 3;
#pragma unroll
    for (int ks = 0; ks < 4; ks++) {
        uint32_t bfr[4][2];
#pragma unroll
        for (int nf2 = 0; nf2 < 2; nf2++) {
            int row = wn * 32 + nf2 * 16 + (lane & 7) + (grp >> 1) * 8;
            int gg  = 2 * ks + (grp & 1);
            uint32_t r[4];
            ldsm4(r, bS + row * 128 + ((gg ^ (row & 7)) << 4));
            bfr[2 * nf2][0] = r[0]; bfr[2 * nf2][1] = r[1];
            bfr[2 * nf2 + 1][0] = r[2]; bfr[2 * nf2 + 1][1] = r[3];
        }
        uint32_t a[2][4];
#pragma unroll
        for (int mf = 0; mf < 2; mf++) {
            int row = wm * 32 + mf * 16 + (lane & 7) + (grp & 1) * 8;
            int gg  = 2 * ks + (grp >> 1);
            ldsm4(a[mf], aS + row * 128 + ((gg ^ (row & 7)) << 4));
        }
#pragma unroll
        for (int mf = 0; mf < 2; mf++)
#pragma unroll
            for (int nf = 0; nf < 4; nf++) {
                if (FIRST && ks == 0) mma_fp16_z(acc[mf][nf], a[mf], bfr[nf]);
                else                  mma_fp16(acc[mf][nf], a[mf], bfr[nf]);
            }
    }
}

// ---------------------------------------------------------------------------
// pass-1 main: fp16 screening, argmax(acc), best-2/slot + top-8/row
// BM=64, BN=128, 64 KB smem, <=84 regs -> 3 CTAs/SM
// ---------------------------------------------------------------------------
__global__ void __launch_bounds__(256, 3)
vq_main() {
    extern __shared__ __align__(16) char smem[];
    const uint32_t sb = smem_u32(smem);
    const int tid = threadIdx.x, lane = tid & 31, wid = tid >> 5;
    const int wm = wid & 1, wn = wid >> 1;   // 2m x 4n warps, warp tile 32x32
    const int rt = blockIdx.x;
    const int n0 = rt * BM;

    float acc[2][4][4];
#pragma unroll
    for (int mf = 0; mf < 2; mf++)
#pragma unroll
        for (int nf = 0; nf < 4; nf++)
#pragma unroll
            for (int r = 0; r < 4; r++) acc[mf][nf][r] = 0.f;

    // best-2 per row-slot (4 slots/thread), ranked by LARGEST acc
    float b1v[4], b2v[4]; int b1i[4], b2i[4];
#pragma unroll
    for (int s = 0; s < 4; s++) {
        b1v[s] = FNEGINF; b2v[s] = FNEGINF; b1i[s] = 0; b2i[s] = 0;
    }

    issueA(sb, rt, tid); issueB(sb, 0, 0, tid); CPC();
    issueB(sb, 1, 1, tid); CPC();

#pragma unroll 1
    for (int g = 0; g < NBSTG; g++) {
        CPW(1);
        __syncthreads();

        const int ti = g >> 2, j = g & 3;
        const uint32_t aS = sb + (uint32_t)j * 8192;
        const uint32_t bS = sb + B_BASE + (g & 1) * B_SLOT;
        if (j == 0) consume<true >(aS, bS, wm, wn, lane, acc);
        else        consume<false>(aS, bS, wm, wn, lane, acc);

        if (j == 3) {
            // argmax insertion (strict >, ascending k -> lowest index on ties)
            const int kbase = ti * BN + wn * 32 + 2 * (lane & 3);
#pragma unroll
            for (int mf = 0; mf < 2; mf++)
#pragma unroll
                for (int h = 0; h < 2; h++) {
                    const int s = mf * 2 + h;
#pragma unroll
                    for (int nf = 0; nf < 4; nf++) {
#pragma unroll
                        for (int q = 0; q < 2; q++) {
                            float a = acc[mf][nf][h * 2 + q];
                            int   k = kbase + nf * 8 + q;
                            if (a > b2v[s]) {
                                if (a > b1v[s]) {
                                    b2v[s] = b1v[s]; b2i[s] = b1i[s];
                                    b1v[s] = a; b1i[s] = k;
                                } else {
                                    b2v[s] = a; b2i[s] = k;
                                }
                            }
                        }
                    }
                }
        }

        __syncthreads();             // WAR guard before refilling the slot
        if (g + 2 < NBSTG) issueB(sb, (g + 2) & 1, g + 2, tid);
        CPC();                       // unconditional: keeps group count aligned
    }

    // dump 32 candidates/row to smem, then per-row top-8 select (by max acc)
    __syncthreads();
    float* rv = (float*)smem;            // 64*32 floats = 8 KB
    int*   ri = (int*)(smem + 8192);     // 8 KB
    const int owner = wn * 4 + (lane & 3);
#pragma unroll
    for (int mf = 0; mf < 2; mf++)
#pragma unroll
        for (int h = 0; h < 2; h++) {
            int row = wm * 32 + mf * 16 + (lane >> 2) + 8 * h;
            int s = mf * 2 + h;
            int base = row * 32 + owner * 2;
            rv[base + 0] = b1v[s]; ri[base + 0] = b1i[s];
            rv[base + 1] = b2v[s]; ri[base + 1] = b2i[s];
        }
    __syncthreads();
    if (tid < BM) {
        const int base = tid * 32;
#pragma unroll 1
        for (int c = 0; c < 8; c++) {
            float bv = FNEGINF; int bi = 0x7fffffff, bj = 0;
            for (int t = 0; t < 32; t++) {
                float v = rv[base + t]; int ii = ri[base + t];
                if (v > bv || (v == bv && ii < bi)) { bv = v; bi = ii; bj = t; }
            }
            g_cand[(size_t)(n0 + tid) * 8 + c] = bi;
            rv[base + bj] = FNEGINF; ri[base + bj] = 0x7fffffff;
        }
    }
}

// ---------------------------------------------------------------------------
// pass-2: exact fp32 distance on 8 candidates/row; pick final idx
//   dist = fl(xs - fl(2*dot))   (e2 proven to vanish: e2 < half-ulp(xs))
// ---------------------------------------------------------------------------
__global__ void vq_exact(const float* __restrict__ emb, float* __restrict__ out) {
    const int w = threadIdx.x >> 5, lane = threadIdx.x & 31;
    const int n = blockIdx.x * 8 + w;
    const float* xr = g_xT + (size_t)n * DD;
    float xv[8];
#pragma unroll
    for (int t = 0; t < 8; t++) xv[t] = xr[lane + 32 * t];
    const float xs = g_xs[n];
    float bv = FINF; int bi = 0x7fffffff;
#pragma unroll 1
    for (int c = 0; c < 8; c++) {
        int k = g_cand[(size_t)n * 8 + c];
        const float* er = emb + (size_t)k * DD;
        float dot = 0.f;
#pragma unroll
        for (int t = 0; t < 8; t++) dot = fmaf(xv[t], er[lane + 32 * t], dot);
#pragma unroll
        for (int o = 16; o > 0; o >>= 1) dot += __shfl_xor_sync(0xffffffffu, dot, o);
        float v = __fsub_rn(xs, __fadd_rn(dot, dot));
        if (v < bv || (v == bv && k < bi)) { bv = v; bi = k; }
    }
    if (lane == 0) {
        g_fidx[n] = bi;
        out[IDX_OFF + n] = (float)bi;
    }
}

// ---------------------------------------------------------------------------
// finalize: gather + straight-through out + loss partial (128 rows per CTA)
// ---------------------------------------------------------------------------
__global__ void vq_fin(const float* __restrict__ x, const float* __restrict__ emb,
                       float* __restrict__ out) {
    __shared__ double dr[256];
    const int tid = threadIdx.x;
    const int n0 = blockIdx.x * 128, b = n0 >> 10, col0 = n0 & 1023;
    const int r  = tid & 127;
    const int dh = tid >> 7;
    const int er = g_fidx[n0 + r];
    const float* embrow = emb + (size_t)er * DD;
    const float* xr   = x + (size_t)b * (DD * 1024) + col0 + r;
    float*       outr = out + OUT_OFF + (size_t)b * (DD * 1024) + col0 + r;
    double lsum = 0.0;
#pragma unroll 4
    for (int dj = 0; dj < 128; dj++) {
        int d = dh * 128 + dj;
        float xp = xr[(size_t)d * 1024];
        float q  = embrow[d];
        float dl = __fsub_rn(q, xp);
        outr[(size_t)d * 1024] = __fadd_rn(xp, dl);
        lsum += (double)__fmul_rn(dl, dl);
    }
    dr[tid] = lsum;
    __syncthreads();
    for (int sft = 128; sft > 0; sft >>= 1) {
        if (tid < sft) dr[tid] += dr[tid + sft];
        __syncthreads();
    }
    if (tid == 0) g_part[blockIdx.x] = dr[0];
}

// ---------------------------------------------------------------------------
// finalize loss (one warp, deterministic)
// ---------------------------------------------------------------------------
__global__ void vq_final(float* __restrict__ out) {
    int l = threadIdx.x;
    double s = 0.0;
    for (int i = l; i < NCTA_FIN; i += 32) s += g_part[i];
#pragma unroll
    for (int o = 16; o > 0; o >>= 1) s += __shfl_xor_sync(0xffffffffu, s, o);
    if (l == 0) {
        float L = (float)(s / (double)((size_t)NN * DD));
        out[LOSS_OFF] = __fadd_rn(L, __fmul_rn(0.25f, L));
    }
}

extern "C" void kernel_launch(void* const* d_in, const int* in_sizes, int n_in,
                              void* d_out, int out_size) {
    const float* x   = (const float*)d_in[0];
    const float* emb = (const float*)d_in[1];
    float* out = (float*)d_out;

    cudaFuncSetAttribute(vq_main, cudaFuncAttributeMaxDynamicSharedMemorySize, SMEM_DYN);

    vq_xs     <<<NN / 256,      256>>>(x);
    vq_split_x<<<1024,          256>>>(x);
    vq_split_e<<<KK / 8,        256>>>(emb);
    vq_main   <<<NCTA_MAIN, 256, SMEM_DYN>>>();
    vq_exact  <<<NN / 8, 256>>>(emb, out);
    vq_fin    <<<NCTA_FIN, 256>>>(x, emb, out);
    vq_final  <<<1, 32>>>(out);
}

// round 16
// speedup vs baseline: 1.1943x; 1.1943x over previous
#include <cuda_runtime.h>
#include <cuda_fp16.h>
#include <cstdint>

// -------------------------- problem constants ------------------------------
#define NN 32768        // rows (B*H*W)
#define DD 256          // embedding dim
#define KK 8192         // codebook size
#define BM 64           // rows per CTA (pass-1)
#define BN 256          // codes per n-tile
#define NTILES (KK / BN)            // 32
#define BSPT 4                      // B-stages per tile (K-chunks of 64)
#define NBSTG (NTILES * BSPT)       // 128
#define NCTA_MAIN (NN / BM)         // 512
#define NCTA_FIN  256               // vq_fin grid (128 rows each)
#define NCAND 4                     // exact-pass candidates per row

#define OUT_OFF  0
#define LOSS_OFF 8388608
#define IDX_OFF  8388609

#define A_BYTES  32768              // 4 h1 chunks x 8 KB, resident
#define B_SLOT   32768              // one c1 chunk: 256 rows x 128 B
#define B_BASE   A_BYTES
#define SMEM_DYN (A_BYTES + 2 * B_SLOT)   // 98304 -> 2 CTAs/SM

#define ESCALE 65536.0f             // e pre-scale 2^16 (exact)
#define FNEGINF __int_as_float(0xff800000)
#define FINF    __int_as_float(0x7f800000)

__device__ float  g_xs[NN];
__device__ float  g_xsp[8 * NN];    // per-d-slice partial |x|^2
__device__ double g_part[NCTA_FIN];
__device__ int    g_cand[NN * NCAND];
__device__ int    g_fidx[NN];
__device__ __align__(16) float  g_xT[(size_t)NN * DD];      // row-major x copy
// fp16 screening operands, chunk-major [chunk][row][64 halves] (128 B/row)
__device__ __align__(16) __half g_Ah[(size_t)4 * NN * 64];  // h1 = fp16(x)
__device__ __align__(16) __half g_Eh[(size_t)4 * KK * 64];  // c1 = fp16(e*2^16)

// ---------------------------- asm helpers ----------------------------------
__device__ __forceinline__ uint32_t smem_u32(const void* p) {
    uint32_t a;
    asm("{ .reg .u64 t; cvta.to.shared.u64 t, %1; cvt.u32.u64 %0, t; }" : "=r"(a) : "l"(p));
    return a;
}
#define CPA(dst, src) asm volatile("cp.async.cg.shared.global [%0], [%1], 16;" :: "r"(dst), "l"(src))
#define CPC()         asm volatile("cp.async.commit_group;" ::: "memory")
#define CPW(n)        asm volatile("cp.async.wait_group %0;" :: "n"(n) : "memory")

__device__ __forceinline__ void ldsm4(uint32_t* r, uint32_t addr) {
    asm volatile("ldmatrix.sync.aligned.m8n8.x4.shared.b16 {%0,%1,%2,%3}, [%4];"
        : "=r"(r[0]), "=r"(r[1]), "=r"(r[2]), "=r"(r[3]) : "r"(addr));
}
__device__ __forceinline__ void mma_fp16(float* c, const uint32_t* a, const uint32_t* b) {
    asm volatile("mma.sync.aligned.m16n8k16.row.col.f32.f16.f16.f32 "
        "{%0,%1,%2,%3}, {%4,%5,%6,%7}, {%8,%9}, {%0,%1,%2,%3};"
        : "+f"(c[0]), "+f"(c[1]), "+f"(c[2]), "+f"(c[3])
        : "r"(a[0]), "r"(a[1]), "r"(a[2]), "r"(a[3]), "r"(b[0]), "r"(b[1]));
}
// D = A*B + 0 (separate zero C: resets the accumulator without MOVs)
__device__ __forceinline__ void mma_fp16_z(float* c, const uint32_t* a, const uint32_t* b) {
    asm volatile("mma.sync.aligned.m16n8k16.row.col.f32.f16.f16.f32 "
        "{%0,%1,%2,%3}, {%4,%5,%6,%7}, {%8,%9}, {%10,%10,%10,%10};"
        : "=f"(c[0]), "=f"(c[1]), "=f"(c[2]), "=f"(c[3])
        : "r"(a[0]), "r"(a[1]), "r"(a[2]), "r"(a[3]), "r"(b[0]), "r"(b[1]), "f"(0.f));
}

// ---------------------------------------------------------------------------
// prep kernels
// ---------------------------------------------------------------------------
// x split: grid 1024 = 8 d-slices(32) x 128 row-blocks(256); smem transpose
// produces: h1 fp16 chunks, g_xT row-major copy, AND per-slice |x|^2 partials
__global__ void vq_split_x(const float* __restrict__ x) {
    __shared__ float sx[32][257];
    const int t  = threadIdx.x;
    const int dc = blockIdx.x & 7;
    const int nb = blockIdx.x >> 3;
    const int n0 = nb * 256;
    const int b  = n0 >> 10, hw0 = n0 & 1023;
    const float* xb = x + (size_t)b * (DD * 1024) + (size_t)(dc * 32) * 1024 + hw0;
#pragma unroll
    for (int dd = 0; dd < 32; dd++) sx[dd][t] = xb[(size_t)dd * 1024 + t];
    __syncthreads();

    // per-slice |x|^2 partial (fixed fmaf order)
    float s = 0.f;
#pragma unroll
    for (int dd = 0; dd < 32; dd++) s = fmaf(sx[dd][t], sx[dd][t], s);
    g_xsp[dc * NN + n0 + t] = s;

    float* xrow = g_xT + (size_t)(n0 + t) * DD + dc * 32;
#pragma unroll
    for (int q = 0; q < 8; q++)
        *(float4*)(xrow + 4 * q) = make_float4(sx[4 * q][t], sx[4 * q + 1][t],
                                               sx[4 * q + 2][t], sx[4 * q + 3][t]);
    uint32_t p1[16];
#pragma unroll
    for (int u = 0; u < 16; u++) {
        uint32_t h0 = (uint32_t)__half_as_ushort(__float2half_rn(sx[2 * u][t]));
        uint32_t h1 = (uint32_t)__half_as_ushort(__float2half_rn(sx[2 * u + 1][t]));
        p1[u] = h0 | (h1 << 16);
    }
    __half* d1 = g_Ah + ((size_t)(dc >> 1) * NN + n0 + t) * 64 + (dc & 1) * 32;
#pragma unroll
    for (int p = 0; p < 4; p++)
        *(uint4*)(d1 + 8 * p) = make_uint4(p1[4 * p], p1[4 * p + 1], p1[4 * p + 2], p1[4 * p + 3]);
}

// reduce the 8 partials per row (deterministic fixed order)
__global__ void vq_xsr() {
    int n = blockIdx.x * blockDim.x + threadIdx.x;
    float s = g_xsp[n];
#pragma unroll
    for (int p = 1; p < 8; p++) s = __fadd_rn(s, g_xsp[p * NN + n]);
    g_xs[n] = s;
}

// emb split: 1 warp per code row; c1 = fp16(e*2^16)
__global__ void vq_split_e(const float* __restrict__ emb) {
    int wid = threadIdx.x >> 5, lane = threadIdx.x & 31;
    int k = blockIdx.x * 8 + wid;
    const float* er = emb + (size_t)k * DD;
#pragma unroll
    for (int dc = 0; dc < 8; dc++) {
        float es = __fmul_rn(er[dc * 32 + lane], ESCALE);
        g_Eh[((size_t)(dc >> 1) * KK + k) * 64 + (dc & 1) * 32 + lane] = __float2half_rn(es);
    }
}

// ---------------------------------------------------------------------------
// issue helpers (XOR-swizzled 16B granules)
// ---------------------------------------------------------------------------
__device__ __forceinline__ void issueA(uint32_t sb, int rt, int tid) {
#pragma unroll
    for (int p = 0; p < 8; p++) {
        int i = tid + p * 256;
        int chunk = i >> 9, gi = i & 511, row = gi >> 3, gg = gi & 7;
        const char* src = (const char*)g_Ah +
            ((size_t)chunk * NN + (size_t)rt * BM + row) * 128 + gg * 16;
        CPA(sb + chunk * 8192 + row * 128 + ((gg ^ (row & 7)) << 4), src);
    }
}
__device__ __forceinline__ void issueB(uint32_t sb, int slot, int g, int tid) {
    const int ti = g >> 2, bc = g & 3;
    const char* bSrc = (const char*)g_Eh + ((size_t)bc * KK + (size_t)ti * BN) * 128;
    const uint32_t bDst = sb + B_BASE + slot * B_SLOT;
#pragma unroll
    for (int p = 0; p < 8; p++) {
        int i = tid + p * 256, row = i >> 3, gg = i & 7;
        CPA(bDst + row * 128 + ((gg ^ (row & 7)) << 4), bSrc + (size_t)i * 16);
    }
}

// consume: one A chunk (64 rows, K=64) vs one B chunk (256 codes)
template <bool FIRST>
__device__ __forceinline__ void consume(uint32_t aS, uint32_t bS, int wm, int wn,
                                        int lane, float (&acc)[2][8][4]) {
    const int grp = lane >> 3;
#pragma unroll
    for (int ks = 0; ks < 4; ks++) {
        uint32_t bfr[8][2];
#pragma unroll
        for (int nf2 = 0; nf2 < 4; nf2++) {
            int row = wn * 64 + nf2 * 16 + (lane & 7) + (grp >> 1) * 8;
            int gg  = 2 * ks + (grp & 1);
            uint32_t r[4];
            ldsm4(r, bS + row * 128 + ((gg ^ (row & 7)) << 4));
            bfr[2 * nf2][0] = r[0]; bfr[2 * nf2][1] = r[1];
            bfr[2 * nf2 + 1][0] = r[2]; bfr[2 * nf2 + 1][1] = r[3];
        }
        uint32_t a[2][4];
#pragma unroll
        for (int mf = 0; mf < 2; mf++) {
            int row = wm * 32 + mf * 16 + (lane & 7) + (grp & 1) * 8;
            int gg  = 2 * ks + (grp >> 1);
            ldsm4(a[mf], aS + row * 128 + ((gg ^ (row & 7)) << 4));
        }
#pragma unroll
        for (int mf = 0; mf < 2; mf++)
#pragma unroll
            for (int nf = 0; nf < 8; nf++) {
                if (FIRST && ks == 0) mma_fp16_z(acc[mf][nf], a[mf], bfr[nf]);
                else                  mma_fp16(acc[mf][nf], a[mf], bfr[nf]);
            }
    }
}

// ---------------------------------------------------------------------------
// pass-1 main: fp16 screening, argmax(acc), best-2/slot + top-4/row
// ---------------------------------------------------------------------------
__global__ void __launch_bounds__(256, 2)
vq_main() {
    extern __shared__ __align__(16) char smem[];
    const uint32_t sb = smem_u32(smem);
    const int tid = threadIdx.x, lane = tid & 31, wid = tid >> 5;
    const int wm = wid & 1, wn = wid >> 1;   // 2m x 4n warps, warp tile 32x64
    const int rt = blockIdx.x;
    const int n0 = rt * BM;

    float acc[2][8][4];
#pragma unroll
    for (int mf = 0; mf < 2; mf++)
#pragma unroll
        for (int nf = 0; nf < 8; nf++)
#pragma unroll
            for (int r = 0; r < 4; r++) acc[mf][nf][r] = 0.f;

    // best-2 per row-slot (4 slots/thread), ranked by LARGEST acc
    float b1v[4], b2v[4]; int b1i[4], b2i[4];
#pragma unroll
    for (int s = 0; s < 4; s++) {
        b1v[s] = FNEGINF; b2v[s] = FNEGINF; b1i[s] = 0; b2i[s] = 0;
    }

    issueA(sb, rt, tid); issueB(sb, 0, 0, tid); CPC();
    issueB(sb, 1, 1, tid); CPC();

#pragma unroll 1
    for (int g = 0; g < NBSTG; g++) {
        CPW(1);
        __syncthreads();

        const int ti = g >> 2, j = g & 3;
        const uint32_t aS = sb + (uint32_t)j * 8192;
        const uint32_t bS = sb + B_BASE + (g & 1) * B_SLOT;
        if (j == 0) consume<true >(aS, bS, wm, wn, lane, acc);
        else        consume<false>(aS, bS, wm, wn, lane, acc);

        if (j == 3) {
            // argmax insertion (strict >, ascending k -> lowest index on ties)
            const int kbase = ti * BN + wn * 64 + 2 * (lane & 3);
#pragma unroll
            for (int mf = 0; mf < 2; mf++)
#pragma unroll
                for (int h = 0; h < 2; h++) {
                    const int s = mf * 2 + h;
#pragma unroll
                    for (int nf = 0; nf < 8; nf++) {
#pragma unroll
                        for (int q = 0; q < 2; q++) {
                            float a = acc[mf][nf][h * 2 + q];
                            int   k = kbase + nf * 8 + q;
                            if (a > b2v[s]) {
                                if (a > b1v[s]) {
                                    b2v[s] = b1v[s]; b2i[s] = b1i[s];
                                    b1v[s] = a; b1i[s] = k;
                                } else {
                                    b2v[s] = a; b2i[s] = k;
                                }
                            }
                        }
                    }
                }
        }

        __syncthreads();             // WAR guard before refilling the slot
        if (g + 2 < NBSTG) issueB(sb, (g + 2) & 1, g + 2, tid);
        CPC();                       // unconditional: keeps group count aligned
    }

    // dump 32 candidates/row to smem, then per-row top-NCAND select (by max acc)
    __syncthreads();
    float* rv = (float*)smem;            // 64*32 floats = 8 KB
    int*   ri = (int*)(smem + 8192);     // 8 KB
    const int owner = wn * 4 + (lane & 3);
#pragma unroll
    for (int mf = 0; mf < 2; mf++)
#pragma unroll
        for (int h = 0; h < 2; h++) {
            int row = wm * 32 + mf * 16 + (lane >> 2) + 8 * h;
            int s = mf * 2 + h;
            int base = row * 32 + owner * 2;
            rv[base + 0] = b1v[s]; ri[base + 0] = b1i[s];
            rv[base + 1] = b2v[s]; ri[base + 1] = b2i[s];
        }
    __syncthreads();
    if (tid < BM) {
        const int base = tid * 32;
#pragma unroll 1
        for (int c = 0; c < NCAND; c++) {
            float bv = FNEGINF; int bi = 0x7fffffff, bj = 0;
            for (int t = 0; t < 32; t++) {
                float v = rv[base + t]; int ii = ri[base + t];
                if (v > bv || (v == bv && ii < bi)) { bv = v; bi = ii; bj = t; }
            }
            g_cand[(size_t)(n0 + tid) * NCAND + c] = bi;
            rv[base + bj] = FNEGINF; ri[base + bj] = 0x7fffffff;
        }
    }
}

// ---------------------------------------------------------------------------
// pass-2: exact fp32 distance on NCAND candidates/row; pick final idx
//   dist = fl(xs - fl(2*dot))   (e2 proven to vanish: e2 < half-ulp(xs))
// ---------------------------------------------------------------------------
__global__ void vq_exact(const float* __restrict__ emb, float* __restrict__ out) {
    const int w = threadIdx.x >> 5, lane = threadIdx.x & 31;
    const int n = blockIdx.x * 8 + w;
    const float* xr = g_xT + (size_t)n * DD;
    float xv[8];
#pragma unroll
    for (int t = 0; t < 8; t++) xv[t] = xr[lane + 32 * t];
    const float xs = g_xs[n];
    float bv = FINF; int bi = 0x7fffffff;
#pragma unroll 1
    for (int c = 0; c < NCAND; c++) {
        int k = g_cand[(size_t)n * NCAND + c];
        const float* er = emb + (size_t)k * DD;
        float dot = 0.f;
#pragma unroll
        for (int t = 0; t < 8; t++) dot = fmaf(xv[t], er[lane + 32 * t], dot);
#pragma unroll
        for (int o = 16; o > 0; o >>= 1) dot += __shfl_xor_sync(0xffffffffu, dot, o);
        float v = __fsub_rn(xs, __fadd_rn(dot, dot));
        if (v < bv || (v == bv && k < bi)) { bv = v; bi = k; }
    }
    if (lane == 0) {
        g_fidx[n] = bi;
        out[IDX_OFF + n] = (float)bi;
    }
}

// ---------------------------------------------------------------------------
// finalize: gather + straight-through out + loss partial (128 rows per CTA)
// ---------------------------------------------------------------------------
__global__ void vq_fin(const float* __restrict__ x, const float* __restrict__ emb,
                       float* __restrict__ out) {
    __shared__ double dr[256];
    const int tid = threadIdx.x;
    const int n0 = blockIdx.x * 128, b = n0 >> 10, col0 = n0 & 1023;
    const int r  = tid & 127;
    const int dh = tid >> 7;
    const int er = g_fidx[n0 + r];
    const float* embrow = emb + (size_t)er * DD;
    const float* xr   = x + (size_t)b * (DD * 1024) + col0 + r;
    float*       outr = out + OUT_OFF + (size_t)b * (DD * 1024) + col0 + r;
    double lsum = 0.0;
#pragma unroll 4
    for (int dj = 0; dj < 128; dj++) {
        int d = dh * 128 + dj;
        float xp = xr[(size_t)d * 1024];
        float q  = embrow[d];
        float dl = __fsub_rn(q, xp);
        outr[(size_t)d * 1024] = __fadd_rn(xp, dl);
        lsum += (double)__fmul_rn(dl, dl);
    }
    dr[tid] = lsum;
    __syncthreads();
    for (int sft = 128; sft > 0; sft >>= 1) {
        if (tid < sft) dr[tid] += dr[tid + sft];
        __syncthreads();
    }
    if (tid == 0) g_part[blockIdx.x] = dr[0];
}

// ---------------------------------------------------------------------------
// finalize loss (one warp, deterministic)
// ---------------------------------------------------------------------------
__global__ void vq_final(float* __restrict__ out) {
    int l = threadIdx.x;
    double s = 0.0;
    for (int i = l; i < NCTA_FIN; i += 32) s += g_part[i];
#pragma unroll
    for (int o = 16; o > 0; o >>= 1) s += __shfl_xor_sync(0xffffffffu, s, o);
    if (l == 0) {
        float L = (float)(s / (double)((size_t)NN * DD));
        out[LOSS_OFF] = __fadd_rn(L, __fmul_rn(0.25f, L));
    }
}

extern "C" void kernel_launch(void* const* d_in, const int* in_sizes, int n_in,
                              void* d_out, int out_size) {
    const float* x   = (const float*)d_in[0];
    const float* emb = (const float*)d_in[1];
    float* out = (float*)d_out;

    cudaFuncSetAttribute(vq_main, cudaFuncAttributeMaxDynamicSharedMemorySize, SMEM_DYN);

    vq_split_x<<<1024,      256>>>(x);
    vq_split_e<<<KK / 8,    256>>>(emb);
    vq_xsr    <<<NN / 256,  256>>>();
    vq_main   <<<NCTA_MAIN, 256, SMEM_DYN>>>();
    vq_exact  <<<NN / 8, 256>>>(emb, out);
    vq_fin    <<<NCTA_FIN, 256>>>(x, emb, out);
    vq_final  <<<1, 32>>>(out);
}